// round 12
// baseline (speedup 1.0000x reference)
#include <cuda_runtime.h>
#include <stdint.h>

#define FULL_MASK 0xFFFFFFFFu

constexpr int   L_     = 9;
constexpr float PADF   = 1e30f;
constexpr int   VOCAB  = 128000;
constexpr int   SENTI  = 1 << 30;
constexpr float INVSQ2 = 0.70710678f;   // 0x3F3504F3, same as numpy complex64 1/sqrt(2)

// Ascending bitonic exchange at lane-stride ST. Key via predicated FMNMX;
// payload moves iff key changed (exact: tied keys carry identical payloads).
#define STAGE(KEY, PAY, ST) do {                                        \
    float    _ok = __shfl_xor_sync(FULL_MASK, (KEY), (ST));             \
    unsigned _op = __shfl_xor_sync(FULL_MASK, (PAY), (ST));             \
    float    _old = (KEY);                                              \
    (KEY) = (lane & (ST)) ? fmaxf(_old, _ok) : fminf(_old, _ok);        \
    if ((KEY) != _old) (PAY) = _op;                                     \
} while (0)

// Key-only exchange (scores only; payload no longer needed).
#define STAGE_K(KEY, ST) do {                                           \
    float _ok = __shfl_xor_sync(FULL_MASK, (KEY), (ST));                \
    (KEY) = (lane & (ST)) ? fmaxf((KEY), _ok) : fminf((KEY), _ok);      \
} while (0)

__global__ __launch_bounds__(256)
void beam_kernel(const float* __restrict__ y, const float* __restrict__ h,
                 float* __restrict__ out, int T, int mode)
{
    int warp = blockIdx.x * (blockDim.x >> 5) + (threadIdx.x >> 5);
    int lane = threadIdx.x & 31;
    int bl   = lane & 15;                 // beam index within half-warp (packed phase)
    int row0 = warp * 2;
    if (row0 >= T) return;
    int row1 = min(row0 + 1, T - 1);

    // ==== UNIFIED FRONT END: both rows in one pass ====
    // lane t (t<9)   -> row0 position t
    // lane 9+t (t<9) -> row1 position t
    size_t ybase = (size_t)row0 * (2 * L_);
    int yoff1 = (row0 + 1 < T) ? (2 * L_) : 0;       // row1 contiguous after row0
    float yv0 = 0.f, yv1 = 0.f;
    if (lane < 2 * L_) {
        yv0 = y[ybase + lane];
        yv1 = y[ybase + yoff1 + lane];
    }
    size_t hbase = (size_t)row0 * 2;
    int hoff1 = (row0 + 1 < T) ? 2 : 0;
    float hv = 0.f;
    if (lane < 4) {
        int idx = (lane < 2) ? lane : (hoff1 + (lane - 2));
        hv = h[hbase + idx];
    }
    float h0 = __shfl_sync(FULL_MASK, hv, 0);
    float h1 = __shfl_sync(FULL_MASK, hv, 1);
    float h2 = __shfl_sync(FULL_MASK, hv, 2);
    float h3 = __shfl_sync(FULL_MASK, hv, 3);

    bool  r0lane = (lane < L_);
    float yi0s = __shfl_sync(FULL_MASK, yv0, lane + 9);   // row0: Im at lane t
    float yr1s = __shfl_sync(FULL_MASK, yv1, lane - 9);   // row1: Re at lane 9+t
    float hr = r0lane ? h0 : h2;
    float hi = r0lane ? h1 : h3;
    float yr = r0lane ? yv0 : yr1s;
    float yi = r0lane ? yi0s : yv1;

    float den = hr * hr + hi * hi;
    float rr  = (yr * hr + yi * hi) / den;
    float ri  = (yi * hr - yr * hi) / den;

    float dist[4];
#pragma unroll
    for (int j = 0; j < 4; ++j) {
        float pr = (j & 1) ? -INVSQ2 : INVSQ2;
        float pi = (j & 2) ? -INVSQ2 : INVSQ2;
        float dr = rr - pr, di = ri - pi;
        dist[j] = dr * dr + di * di;
    }
    int i0 = 0; float dlo = dist[0];
#pragma unroll
    for (int j = 1; j < 4; ++j) if (dist[j] < dlo) { dlo = dist[j]; i0 = j; }
    int i1 = 0; float dhi = __int_as_float(0x7f800000);
#pragma unroll
    for (int j = 0; j < 4; ++j) if (j != i0 && dist[j] < dhi) { dhi = dist[j]; i1 = j; }
    int ip = i0 | (i1 << 2);
    // dlo/dhi/ip valid on lanes 0..17 (row0: 0..8, row1: 9..17)

    // ==== PACKED PHASE (steps 0..3): row0 -> lanes 0..15, row1 -> lanes 16..31 ====
    int rowOff = (lane >= 16) ? L_ : 0;   // shuffle-source offset for my half's row
    float key; unsigned pp;
    {   // step 0: trivial (d0 <= d1 by construction); path accumulates MSB-first
        float d0 = __shfl_sync(FULL_MASK, dlo, rowOff);
        float d1 = __shfl_sync(FULL_MASK, dhi, rowOff);
        int   jj = __shfl_sync(FULL_MASK, ip,  rowOff);
        key = (bl == 0) ? d0 : (bl == 1) ? d1 : PADF;
        pp  = (bl == 0) ? (unsigned)(jj & 3)
            : (bl == 1) ? (unsigned)((jj >> 2) & 3) : 0u;
    }

#pragma unroll
    for (int t = 1; t < 4; ++t) {         // steps 1..3: strides <= 8 stay inside halves
        int srcPos = t + rowOff;          // variable-srcLane broadcast per half
        float d0 = __shfl_sync(FULL_MASK, dlo, srcPos);
        float d1 = __shfl_sync(FULL_MASK, dhi, srcPos);
        int   jj = __shfl_sync(FULL_MASK, ip,  srcPos);
        unsigned c0 = (unsigned)(jj & 3);
        unsigned c1 = (unsigned)((jj >> 2) & 3);

        const int W = 1 << t;             // finite beams entering this step (per row)
        int src  = (bl < W) ? bl : (bl ^ (2 * W - 1));
        int gsrc = (lane & 16) | src;
        float    ss = __shfl_sync(FULL_MASK, key, gsrc);
        unsigned sp = __shfl_sync(FULL_MASK, pp,  gsrc);
        if (bl < W)          { key = ss + d0; pp = sp * 4u + c0; }
        else if (bl < 2 * W) { key = ss + d1; pp = sp * 4u + c1; }
        else                 { key = PADF;    pp = 0u; }
#pragma unroll
        for (int st = 8; st >= 1; st >>= 1)
            if (st <= W) STAGE(key, pp, st);
    }

    // ---- marshal out: per-row full-warp state (beams 0..15 live in lanes 0..15) ----
    float s[2]; unsigned pay[2];
    s[0]   = __shfl_sync(FULL_MASK, key, bl);
    s[1]   = __shfl_sync(FULL_MASK, key, 16 | bl);
    pay[0] = __shfl_sync(FULL_MASK, pp,  bl);
    pay[1] = __shfl_sync(FULL_MASK, pp,  16 | bl);

    // ==== step 4: expand 16 -> 32 per row, merge width 32, rows interleaved ====
    {
#pragma unroll
        for (int q = 0; q < 2; ++q) {
            float d0 = __shfl_sync(FULL_MASK, dlo, 4 + 9 * q);
            float d1 = __shfl_sync(FULL_MASK, dhi, 4 + 9 * q);
            int   ii = __shfl_sync(FULL_MASK, ip,  4 + 9 * q);
            int src = (lane < 16) ? lane : (lane ^ 31);
            float    ss = __shfl_sync(FULL_MASK, s[q], src);
            unsigned sp = __shfl_sync(FULL_MASK, pay[q], src);
            if (lane < 16) { s[q] = ss + d0; pay[q] = sp * 4u + (unsigned)(ii & 3); }
            else           { s[q] = ss + d1; pay[q] = sp * 4u + (unsigned)((ii >> 2) & 3); }
        }
#pragma unroll
        for (int st = 16; st >= 1; st >>= 1) {
#pragma unroll
            for (int q = 0; q < 2; ++q) STAGE(s[q], pay[q], st);
        }
    }

    // ==== steps 5..7: half-cleaner + full merge, with payload ====
#pragma unroll
    for (int t = 5; t < 8; ++t) {
#pragma unroll
        for (int q = 0; q < 2; ++q) {
            float d0 = __shfl_sync(FULL_MASK, dlo, t + 9 * q);
            float d1 = __shfl_sync(FULL_MASK, dhi, t + 9 * q);
            int   ii = __shfl_sync(FULL_MASK, ip,  t + 9 * q);
            float    sB  = __shfl_xor_sync(FULL_MASK, s[q], 31);
            unsigned pB0 = __shfl_xor_sync(FULL_MASK, pay[q], 31);
            float kA = s[q] + d0, kB = sB + d1;
            unsigned pA = pay[q] * 4u + (unsigned)(ii & 3);
            unsigned pB = pB0   * 4u + (unsigned)((ii >> 2) & 3);
            bool takeB = kB < kA;
            s[q]   = takeB ? kB : kA;
            pay[q] = takeB ? pB : pA;
        }
#pragma unroll
        for (int st = 16; st >= 1; st >>= 1) {
#pragma unroll
            for (int q = 0; q < 2; ++q) STAGE(s[q], pay[q], st);
        }
    }

    // ==== step 8: half-cleaner fixes the final top-32 SET (payload final here);
    //      remaining stages sort scores only (ids re-sorted in epilogue anyway) ====
    int v[2];
#pragma unroll
    for (int q = 0; q < 2; ++q) {
        float d0 = __shfl_sync(FULL_MASK, dlo, 8 + 9 * q);
        float d1 = __shfl_sync(FULL_MASK, dhi, 8 + 9 * q);
        int   ii = __shfl_sync(FULL_MASK, ip,  8 + 9 * q);
        float    sB  = __shfl_xor_sync(FULL_MASK, s[q], 31);
        unsigned pB0 = __shfl_xor_sync(FULL_MASK, pay[q], 31);
        float kA = s[q] + d0, kB = sB + d1;
        unsigned pA = pay[q] * 4u + (unsigned)(ii & 3);
        unsigned pB = pB0   * 4u + (unsigned)((ii >> 2) & 3);
        bool takeB = kB < kA;
        s[q] = takeB ? kB : kA;
        unsigned pfin = takeB ? pB : pA;
        int id = (int)(pfin >> 1);            // exact 17-bit id (MSB-first path >> 1)
        v[q] = (id < VOCAB) ? id : SENTI;     // all 32 beams finite by now
    }
#pragma unroll
    for (int st = 16; st >= 1; st >>= 1) {
        STAGE_K(s[0], st);
        STAGE_K(s[1], st);
    }

    // ==== epilogue: bitonic sort ids ascending (rows interleaved), dedup, compact ====
#pragma unroll
    for (int k = 2; k <= 32; k <<= 1) {
#pragma unroll
        for (int j = k >> 1; j >= 1; j >>= 1) {
            bool keepMin = (((lane & k) == 0) == ((lane & j) == 0));
#pragma unroll
            for (int q = 0; q < 2; ++q) {
                int o = __shfl_xor_sync(FULL_MASK, v[q], j);
                v[q] = keepMin ? min(v[q], o) : max(v[q], o);
            }
        }
    }

    int rows2[2] = { row0, row1 };
#pragma unroll
    for (int q = 0; q < 2; ++q) {
        int  prev = __shfl_up_sync(FULL_MASK, v[q], 1);
        bool keep = (v[q] != SENTI) && (lane == 0 || v[q] != prev);
        unsigned m = __ballot_sync(FULL_MASK, keep);
        unsigned srcbit = __fns(m, 0, lane + 1);
        int shv   = __shfl_sync(FULL_MASK, v[q], (int)(srcbit & 31));
        int outid = (srcbit == 0xFFFFFFFFu) ? -1 : shv;

        size_t base = (size_t)rows2[q] * 32 + lane;
        if (mode == 2) {
            out[base] = (float)outid;           // ids as float32 (exact: |id| < 2^17)
            out[(size_t)T * 32 + base] = s[q];  // scores ascending
        } else {
            ((int*)out)[base] = outid;
        }
    }
}

extern "C" void kernel_launch(void* const* d_in, const int* in_sizes, int n_in,
                              void* d_out, int out_size)
{
    const float* y = (const float*)d_in[0];
    const float* h = (const float*)d_in[1];
    int T = in_sizes[0] / (2 * L_);
    int mode = (out_size >= T * 64) ? 2 : 1;
    int warpsPerBlock = 8;
    int nwarps = (T + 1) / 2;
    int blocks = (nwarps + warpsPerBlock - 1) / warpsPerBlock;
    beam_kernel<<<blocks, warpsPerBlock * 32>>>(y, h, (float*)d_out, T, mode);
}